// round 1
// baseline (speedup 1.0000x reference)
#include <cuda_runtime.h>
#include <cuda_bf16.h>

#define NN    6000
#define DEG   16
#define MM    17      // DEG+1
#define NT    16
#define MT    10
#define MTP   12      // padded row
#define NF    128
#define REGc  0.1f

// ---------------- device scratch (no cudaMalloc allowed) ----------------
__device__ int      g_nbrs[NN * MM];
__device__ unsigned g_B[NN * MM];
__device__ unsigned g_mask[NN * MM];
__device__ float    g_f2n[NT * MT];
__device__ float    g_consts[3];   // cA = 2a/REG, cY = 4a/REG, cM = (1-a)/REG

// ---------------- setup: constants + |F2|^2 ----------------
__global__ void k_setup(const float* __restrict__ alpha0,
                        const float* __restrict__ F2) {
    int tid = threadIdx.x;
    if (tid == 0) {
        float a0 = alpha0[0];
        float alpha = 1.0f / (1.0f + __expf(-a0));
        g_consts[0] = 2.0f * alpha / REGc;
        g_consts[1] = 4.0f * alpha / REGc;
        g_consts[2] = (1.0f - alpha) / REGc;
    }
    for (int idx = tid; idx < NT * MT; idx += blockDim.x) {
        const float* row = F2 + (size_t)idx * NF;
        float s = 0.f;
        #pragma unroll 8
        for (int f = 0; f < NF; f++) { float v = row[f]; s += v * v; }
        g_f2n[idx] = s;
    }
}

// ---------------- build directed-adjacency bitmasks B ----------------
// B[n][i] bit j  <=>  nbrs[n][j] is in dst-row of nbrs[n][i]
__global__ void k_buildB(const int* __restrict__ dst) {
    int gid = blockIdx.x * blockDim.x + threadIdx.x;
    if (gid >= NN * MM) return;
    int n = gid / MM;
    int i = gid - n * MM;
    const int* dstn = dst + (size_t)n * DEG;
    int u = (i == 0) ? n : dstn[i - 1];
    g_nbrs[gid] = u;

    const int* dstu = dst + (size_t)u * DEG;
    int du[DEG];
    #pragma unroll
    for (int e = 0; e < DEG; e++) du[e] = dstu[e];

    int dn[DEG];
    #pragma unroll
    for (int e = 0; e < DEG; e++) dn[e] = dstn[e];

    unsigned bits = 0;
    #pragma unroll
    for (int j = 0; j < MM; j++) {
        int v = (j == 0) ? n : dn[j - 1];
        bool hit = false;
        #pragma unroll
        for (int e = 0; e < DEG; e++) hit |= (du[e] == v);
        bits |= (unsigned)hit << j;
    }
    g_B[gid] = bits;
}

// ---------------- symmetrize: C1 = B | B^T  (per-node 17x17) ----------------
__global__ void k_sym() {
    int gid = blockIdx.x * blockDim.x + threadIdx.x;
    if (gid >= NN * MM) return;
    int n = gid / MM;
    int i = gid - n * MM;
    unsigned mk = g_B[gid];
    const unsigned* Bn = g_B + n * MM;
    #pragma unroll
    for (int j = 0; j < MM; j++)
        mk |= ((Bn[j] >> i) & 1u) << j;
    g_mask[gid] = mk;
}

// ---------------- main: Mcost + 10 mirror-descent iters + q ----------------
__global__ void __launch_bounds__(272, 2)
k_main(const float* __restrict__ x,
       const float* __restrict__ C2g,   // templates  (NT,MT,MT)
       const float* __restrict__ F2,    // templates_features (NT,MT,NF)
       float* __restrict__ out) {
    __shared__ float sF1[MM][NF + 4];          // padded vs bank conflicts
    __shared__ float sT [NT][MM][MTP];
    __shared__ float sq [NT][MT];
    __shared__ float scc[NT][MT];
    __shared__ float sC2 [NT][MT][MTP];
    __shared__ float sC2s[NT][MT][MTP];

    const int tid = threadIdx.x;
    const int n   = blockIdx.x;
    const int k   = tid / MM;
    const int m   = tid - k * MM;

    // cooperative load of C2 / C2^2 into padded smem
    for (int idx = tid; idx < NT * MT * MTP; idx += 272) {
        int kk = idx / (MT * MTP);
        int r  = idx - kk * MT * MTP;
        int s  = r / MTP;
        int t  = r - s * MTP;
        float v = (t < MT) ? C2g[(kk * MT + s) * MT + t] : 0.f;
        ((float*)sC2)[idx]  = v;
        ((float*)sC2s)[idx] = v * v;
    }
    // cooperative gather of F1 = x[nbrs] into smem (float4)
    for (int idx = tid; idx < MM * (NF / 4); idx += 272) {
        int r = idx >> 5;
        int c = idx & 31;
        int u = g_nbrs[n * MM + r];
        float4 v = __ldg((const float4*)(x + (size_t)u * NF) + c);
        *(float4*)&sF1[r][c * 4] = v;
    }
    __syncthreads();

    // ---- Mcost: thread (k,m) computes dot(F1[m], F2[k][t]) for t=0..9 ----
    float acc[MT];
    #pragma unroll
    for (int t = 0; t < MT; t++) acc[t] = 0.f;
    float n1 = 0.f;
    const float* F2k = F2 + (size_t)k * MT * NF;
    for (int fc = 0; fc < NF / 4; fc++) {
        float4 a = *(const float4*)&sF1[m][fc * 4];
        n1 += a.x * a.x + a.y * a.y + a.z * a.z + a.w * a.w;
        #pragma unroll
        for (int t = 0; t < MT; t++) {
            float4 b = __ldg((const float4*)(F2k + t * NF) + fc);
            acc[t] += a.x * b.x + a.y * b.y + a.z * b.z + a.w * b.w;
        }
    }

    const float cA = g_consts[0];
    const float cY = g_consts[1];
    const float cM = g_consts[2];

    const unsigned mask = g_mask[n * MM + m];
    const float c1p = (float)__popc(mask) * (1.0f / MM);
    float basec[MT];
    #pragma unroll
    for (int t = 0; t < MT; t++)
        basec[t] = cM * (n1 + g_f2n[k * MT + t] - 2.0f * acc[t]) + cA * c1p;

    const unsigned resmask = (m == 0) ? 0u : (mask & ~1u);
    const float c00w = (mask & 1u) ? 0.f : -1.f;   // (C1[0,0] - 1)

    float lt[MT];
    #pragma unroll
    for (int t = 0; t < MT; t++) lt[t] = 0.f;      // constant init shift irrelevant

    float e[MT];
    float Y[MT];

    #pragma unroll 1
    for (int it = 0; it < 10; it++) {
        // softmax row (in registers), T = p * softmax
        float mx = lt[0];
        #pragma unroll
        for (int t = 1; t < MT; t++) mx = fmaxf(mx, lt[t]);
        float ssum = 0.f;
        #pragma unroll
        for (int t = 0; t < MT; t++) { e[t] = __expf(lt[t] - mx); ssum += e[t]; }
        float pr = (1.0f / MM) / ssum;
        #pragma unroll
        for (int t = 0; t < MT; t++) e[t] *= pr;

        float* Trow = &sT[k][m][0];
        ((float4*)Trow)[0] = make_float4(e[0], e[1], e[2], e[3]);
        ((float4*)Trow)[1] = make_float4(e[4], e[5], e[6], e[7]);
        ((float2*)Trow)[4] = make_float2(e[8], e[9]);
        __syncthreads();

        // q[t]: lanes m<10 each own one t
        if (m < MT) {
            float qv = 0.f;
            #pragma unroll
            for (int b = 0; b < MM; b++) qv += sT[k][b][m];
            sq[k][m] = qv;
        }
        // Y rows for m>=1: T0 + sparse residual (all sT reads happen here)
        if (m > 0) {
            #pragma unroll
            for (int t = 0; t < MT; t++) Y[t] = sT[k][0][t];
            unsigned rm = resmask;
            while (rm) {
                int b = __ffs(rm) - 1;
                rm &= rm - 1;
                #pragma unroll
                for (int t = 0; t < MT; t++) Y[t] += sT[k][b][t];
            }
        }
        __syncthreads();

        // constC2[s]: lanes m<10
        if (m < MT) {
            float cc = 0.f;
            #pragma unroll
            for (int b = 0; b < MT; b++) cc += sq[k][b] * sC2s[k][m][b];
            scc[k][m] = cc;
        }
        // Y row for m==0: q + (C1_00 - 1) * T0   (own T row == T0)
        if (m == 0) {
            #pragma unroll
            for (int t = 0; t < MT; t++) Y[t] = sq[k][t] + c00w * e[t];
        }
        __syncthreads();

        // update: lt[s] += cY*(Y·C2[s]) - cA*constC2[s] - (cA*c1p + cM*Mc[s])
        #pragma unroll
        for (int s = 0; s < MT; s++) {
            float y2 = 0.f;
            #pragma unroll
            for (int t = 0; t < MT; t++) y2 += Y[t] * sC2[k][s][t];
            lt[s] += cY * y2 - cA * scc[k][s] - basec[s];
        }
    }

    // final marginal q from one more softmax
    {
        float mx = lt[0];
        #pragma unroll
        for (int t = 1; t < MT; t++) mx = fmaxf(mx, lt[t]);
        float ssum = 0.f;
        #pragma unroll
        for (int t = 0; t < MT; t++) { e[t] = __expf(lt[t] - mx); ssum += e[t]; }
        float pr = (1.0f / MM) / ssum;
        #pragma unroll
        for (int t = 0; t < MT; t++) e[t] *= pr;
        float* Trow = &sT[k][m][0];
        ((float4*)Trow)[0] = make_float4(e[0], e[1], e[2], e[3]);
        ((float4*)Trow)[1] = make_float4(e[4], e[5], e[6], e[7]);
        ((float2*)Trow)[4] = make_float2(e[8], e[9]);
        __syncthreads();
        if (m < MT) {
            float qv = 0.f;
            #pragma unroll
            for (int b = 0; b < MM; b++) qv += sT[k][b][m];
            out[(size_t)n * (NT * MT) + k * MT + m] = qv;
        }
    }
}

// ---------------- launch ----------------
extern "C" void kernel_launch(void* const* d_in, const int* in_sizes, int n_in,
                              void* d_out, int out_size) {
    const float* x      = (const float*)d_in[0];
    const int*   eidx   = (const int*)d_in[1];
    const float* C2g    = (const float*)d_in[2];
    const float* F2     = (const float*)d_in[3];
    const float* alpha0 = (const float*)d_in[4];
    float* out = (float*)d_out;

    const int* dst = eidx + NN * DEG;   // row 1 of edge_index

    k_setup<<<1, 256>>>(alpha0, F2);
    int tot = NN * MM;
    k_buildB<<<(tot + 127) / 128, 128>>>(dst);
    k_sym<<<(tot + 127) / 128, 128>>>();
    k_main<<<NN, 272>>>(x, C2g, F2, out);
}

// round 2
// speedup vs baseline: 1.7121x; 1.7121x over previous
#include <cuda_runtime.h>
#include <cuda_bf16.h>

#define NN    6000
#define DEG   16
#define MM    17      // DEG+1
#define NT    16
#define MT    10
#define MTP   12      // padded row
#define NF    128
#define NKT   (NT*MT) // 160
#define REGc  0.1f

// ---------------- device scratch (no cudaMalloc allowed) ----------------
__device__ int      g_nbrs[NN * MM];
__device__ unsigned g_B[NN * MM];
__device__ unsigned g_mask[NN * MM];
__device__ float    g_f2n[NKT];
__device__ float    g_consts[3];     // cA = 2a/REG, cY = 4a/REG, cM = (1-a)/REG
__device__ float    g_D[NN * NKT];   // cM*(f2n[kt] - 2 * x[u] . F2[kt])

// ---------------- setup: constants + |F2|^2 ----------------
__global__ void k_setup(const float* __restrict__ alpha0,
                        const float* __restrict__ F2) {
    int tid = threadIdx.x;
    if (tid == 0) {
        float a0 = alpha0[0];
        float alpha = 1.0f / (1.0f + __expf(-a0));
        g_consts[0] = 2.0f * alpha / REGc;
        g_consts[1] = 4.0f * alpha / REGc;
        g_consts[2] = (1.0f - alpha) / REGc;
    }
    for (int idx = tid; idx < NKT; idx += blockDim.x) {
        const float* row = F2 + (size_t)idx * NF;
        float s = 0.f;
        #pragma unroll 8
        for (int f = 0; f < NF; f++) { float v = row[f]; s += v * v; }
        g_f2n[idx] = s;
    }
}

// ---------------- GEMM: D' = cM*(f2n - 2 * x @ F2^T)  (6000x128 @ 128x160) ----
// Tile: 64 rows x 160 cols per block, thread = (tr 0..15, tc 0..15), 4x10 regs.
__global__ void __launch_bounds__(256, 4)
k_gemm(const float* __restrict__ x, const float* __restrict__ F2) {
    __shared__ float sX[32][65];    // [kk][row], pad 65 -> conflict-free
    __shared__ float sF[32][161];   // [kk][col]

    const int tid = threadIdx.x;
    const int tr  = tid & 15;
    const int tc  = tid >> 4;
    const int r0  = blockIdx.x * 64;

    float acc[4][10];
    #pragma unroll
    for (int i = 0; i < 4; i++)
        #pragma unroll
        for (int j = 0; j < 10; j++) acc[i][j] = 0.f;

    for (int k0 = 0; k0 < NF; k0 += 32) {
        __syncthreads();
        // X chunk: 64 rows x 32 k  (512 float4)
        for (int idx = tid; idx < 512; idx += 256) {
            int rr = idx >> 3, c4 = idx & 7;
            int gr = r0 + rr;
            float4 v = (gr < NN) ? __ldg((const float4*)(x + (size_t)gr * NF + k0) + c4)
                                 : make_float4(0.f, 0.f, 0.f, 0.f);
            sX[c4*4+0][rr] = v.x; sX[c4*4+1][rr] = v.y;
            sX[c4*4+2][rr] = v.z; sX[c4*4+3][rr] = v.w;
        }
        // F2 chunk: 160 cols x 32 k (1280 float4)
        for (int idx = tid; idx < 1280; idx += 256) {
            int cc = idx >> 3, c4 = idx & 7;
            float4 v = __ldg((const float4*)(F2 + (size_t)cc * NF + k0) + c4);
            sF[c4*4+0][cc] = v.x; sF[c4*4+1][cc] = v.y;
            sF[c4*4+2][cc] = v.z; sF[c4*4+3][cc] = v.w;
        }
        __syncthreads();

        #pragma unroll 4
        for (int kk = 0; kk < 32; kk++) {
            float b[10];
            #pragma unroll
            for (int j = 0; j < 10; j++) b[j] = sF[kk][tc*10 + j];
            #pragma unroll
            for (int i = 0; i < 4; i++) {
                float a = sX[kk][tr + 16*i];
                #pragma unroll
                for (int j = 0; j < 10; j++) acc[i][j] = fmaf(a, b[j], acc[i][j]);
            }
        }
    }

    const float cM = g_consts[2];
    float f2c[10];
    #pragma unroll
    for (int j = 0; j < 10; j++) f2c[j] = g_f2n[tc*10 + j];
    #pragma unroll
    for (int i = 0; i < 4; i++) {
        int r = r0 + tr + 16*i;
        if (r < NN) {
            float* drow = g_D + (size_t)r * NKT + tc*10;
            #pragma unroll
            for (int j = 0; j < 10; j++)
                drow[j] = cM * (f2c[j] - 2.0f * acc[i][j]);
        }
    }
}

// ---------------- build directed-adjacency bitmasks B ----------------
__global__ void k_buildB(const int* __restrict__ dst) {
    int gid = blockIdx.x * blockDim.x + threadIdx.x;
    if (gid >= NN * MM) return;
    int n = gid / MM;
    int i = gid - n * MM;
    const int* dstn = dst + (size_t)n * DEG;
    int u = (i == 0) ? n : dstn[i - 1];
    g_nbrs[gid] = u;

    const int* dstu = dst + (size_t)u * DEG;
    int du[DEG];
    #pragma unroll
    for (int e = 0; e < DEG; e++) du[e] = dstu[e];
    int dn[DEG];
    #pragma unroll
    for (int e = 0; e < DEG; e++) dn[e] = dstn[e];

    unsigned bits = 0;
    #pragma unroll
    for (int j = 0; j < MM; j++) {
        int v = (j == 0) ? n : dn[j - 1];
        bool hit = false;
        #pragma unroll
        for (int e = 0; e < DEG; e++) hit |= (du[e] == v);
        bits |= (unsigned)hit << j;
    }
    g_B[gid] = bits;
}

// ---------------- symmetrize: C1 = B | B^T ----------------
__global__ void k_sym() {
    int gid = blockIdx.x * blockDim.x + threadIdx.x;
    if (gid >= NN * MM) return;
    int n = gid / MM;
    int i = gid - n * MM;
    unsigned mk = g_B[gid];
    const unsigned* Bn = g_B + n * MM;
    #pragma unroll
    for (int j = 0; j < MM; j++)
        mk |= ((Bn[j] >> i) & 1u) << j;
    g_mask[gid] = mk;
}

// ---------------- main: 10 mirror-descent iters + q ----------------
__global__ void __launch_bounds__(272, 3)
k_main(const float* __restrict__ C2g,   // templates (NT,MT,MT)
       float* __restrict__ out) {
    __shared__ float sT [NT][MM][MTP];
    __shared__ float sq [NT][MT];
    __shared__ float scc[NT][MT];
    __shared__ float sC2 [NT][MT][MTP];
    __shared__ float sC2s[NT][MT][MTP];

    const int tid = threadIdx.x;
    const int n   = blockIdx.x;
    const int k   = tid / MM;
    const int m   = tid - k * MM;

    // cooperative load of C2 / C2^2 into padded smem
    for (int idx = tid; idx < NT * MT * MTP; idx += 272) {
        int kk = idx / (MT * MTP);
        int r  = idx - kk * MT * MTP;
        int s  = r / MTP;
        int t  = r - s * MTP;
        float v = (t < MT) ? C2g[(kk * MT + s) * MT + t] : 0.f;
        ((float*)sC2)[idx]  = v;
        ((float*)sC2s)[idx] = v * v;
    }

    const float cA = g_consts[0];
    const float cY = g_consts[1];

    // per-thread t-varying cost term (t-constant parts cancel in softmax)
    const int u = g_nbrs[n * MM + m];
    float basec[MT];
    {
        const float2* drow = (const float2*)(g_D + (size_t)u * NKT + k * MT);
        #pragma unroll
        for (int h = 0; h < 5; h++) {
            float2 v = __ldg(drow + h);
            basec[2*h]   = v.x;
            basec[2*h+1] = v.y;
        }
    }

    const unsigned mask = g_mask[n * MM + m];
    const unsigned resmask = (m == 0) ? 0u : (mask & ~1u);
    const float c00w = (mask & 1u) ? 0.f : -1.f;   // (C1[0,0] - 1)

    float lt[MT];
    #pragma unroll
    for (int t = 0; t < MT; t++) lt[t] = 0.f;

    float e[MT];
    float Y[MT];

    __syncthreads();

    #pragma unroll 1
    for (int it = 0; it < 10; it++) {
        // softmax row in registers; T = p * softmax
        float mx = lt[0];
        #pragma unroll
        for (int t = 1; t < MT; t++) mx = fmaxf(mx, lt[t]);
        float ssum = 0.f;
        #pragma unroll
        for (int t = 0; t < MT; t++) { e[t] = __expf(lt[t] - mx); ssum += e[t]; }
        float pr = (1.0f / MM) / ssum;
        #pragma unroll
        for (int t = 0; t < MT; t++) e[t] *= pr;

        float* Trow = &sT[k][m][0];
        ((float4*)Trow)[0] = make_float4(e[0], e[1], e[2], e[3]);
        ((float4*)Trow)[1] = make_float4(e[4], e[5], e[6], e[7]);
        ((float2*)Trow)[4] = make_float2(e[8], e[9]);
        __syncthreads();

        // q[t]: lanes m<10 each own one t
        if (m < MT) {
            float qv = 0.f;
            #pragma unroll
            for (int b = 0; b < MM; b++) qv += sT[k][b][m];
            sq[k][m] = qv;
        }
        // Y rows for m>=1: T0 + sparse residual (vectorized reads)
        if (m > 0) {
            const float4* t0 = (const float4*)&sT[k][0][0];
            float4 a = t0[0], b4 = t0[1];
            float2 c = *(const float2*)&sT[k][0][8];
            Y[0]=a.x; Y[1]=a.y; Y[2]=a.z; Y[3]=a.w;
            Y[4]=b4.x; Y[5]=b4.y; Y[6]=b4.z; Y[7]=b4.w;
            Y[8]=c.x; Y[9]=c.y;
            unsigned rm = resmask;
            while (rm) {
                int b = __ffs(rm) - 1;
                rm &= rm - 1;
                const float4* tb = (const float4*)&sT[k][b][0];
                float4 p0 = tb[0], p1 = tb[1];
                float2 p2 = *(const float2*)&sT[k][b][8];
                Y[0]+=p0.x; Y[1]+=p0.y; Y[2]+=p0.z; Y[3]+=p0.w;
                Y[4]+=p1.x; Y[5]+=p1.y; Y[6]+=p1.z; Y[7]+=p1.w;
                Y[8]+=p2.x; Y[9]+=p2.y;
            }
        }
        __syncthreads();

        // constC2[s]: lanes m<10 (vectorized row reads)
        if (m < MT) {
            const float4* r0 = (const float4*)&sC2s[k][m][0];
            float4 a = r0[0], b4 = r0[1];
            float2 c = *(const float2*)&sC2s[k][m][8];
            float cc = sq[k][0]*a.x + sq[k][1]*a.y + sq[k][2]*a.z + sq[k][3]*a.w
                     + sq[k][4]*b4.x + sq[k][5]*b4.y + sq[k][6]*b4.z + sq[k][7]*b4.w
                     + sq[k][8]*c.x + sq[k][9]*c.y;
            scc[k][m] = cc;
        }
        // Y row for m==0: q + (C1_00 - 1) * T0
        if (m == 0) {
            #pragma unroll
            for (int t = 0; t < MT; t++) Y[t] = sq[k][t] + c00w * e[t];
        }
        __syncthreads();

        // update: lt[s] += cY*(Y . C2[s]) - cA*constC2[s] - basec[s]
        float sc[MT];
        {
            const float2* sr = (const float2*)&scc[k][0];
            #pragma unroll
            for (int h = 0; h < 5; h++) {
                float2 v = sr[h];
                sc[2*h] = v.x; sc[2*h+1] = v.y;
            }
        }
        #pragma unroll
        for (int s = 0; s < MT; s++) {
            const float4* r0 = (const float4*)&sC2[k][s][0];
            float4 a = r0[0], b4 = r0[1];
            float2 c = *(const float2*)&sC2[k][s][8];
            float y2 = Y[0]*a.x + Y[1]*a.y + Y[2]*a.z + Y[3]*a.w
                     + Y[4]*b4.x + Y[5]*b4.y + Y[6]*b4.z + Y[7]*b4.w
                     + Y[8]*c.x + Y[9]*c.y;
            lt[s] += cY * y2 - cA * sc[s] - basec[s];
        }
    }

    // final marginal q from one more softmax
    {
        float mx = lt[0];
        #pragma unroll
        for (int t = 1; t < MT; t++) mx = fmaxf(mx, lt[t]);
        float ssum = 0.f;
        #pragma unroll
        for (int t = 0; t < MT; t++) { e[t] = __expf(lt[t] - mx); ssum += e[t]; }
        float pr = (1.0f / MM) / ssum;
        #pragma unroll
        for (int t = 0; t < MT; t++) e[t] *= pr;
        float* Trow = &sT[k][m][0];
        ((float4*)Trow)[0] = make_float4(e[0], e[1], e[2], e[3]);
        ((float4*)Trow)[1] = make_float4(e[4], e[5], e[6], e[7]);
        ((float2*)Trow)[4] = make_float2(e[8], e[9]);
        __syncthreads();
        if (m < MT) {
            float qv = 0.f;
            #pragma unroll
            for (int b = 0; b < MM; b++) qv += sT[k][b][m];
            out[(size_t)n * NKT + k * MT + m] = qv;
        }
    }
}

// ---------------- launch ----------------
extern "C" void kernel_launch(void* const* d_in, const int* in_sizes, int n_in,
                              void* d_out, int out_size) {
    const float* x      = (const float*)d_in[0];
    const int*   eidx   = (const int*)d_in[1];
    const float* C2g    = (const float*)d_in[2];
    const float* F2     = (const float*)d_in[3];
    const float* alpha0 = (const float*)d_in[4];
    float* out = (float*)d_out;

    const int* dst = eidx + NN * DEG;   // row 1 of edge_index

    k_setup<<<1, 256>>>(alpha0, F2);
    k_gemm<<<(NN + 63) / 64, 256>>>(x, F2);
    int tot = NN * MM;
    k_buildB<<<(tot + 127) / 128, 128>>>(dst);
    k_sym<<<(tot + 127) / 128, 128>>>();
    k_main<<<NN, 272>>>(C2g, out);
}

// round 3
// speedup vs baseline: 2.1617x; 1.2626x over previous
#include <cuda_runtime.h>
#include <cuda_bf16.h>

#define NN    6000
#define DEG   16
#define MM    17      // DEG+1
#define NT    16
#define MT    10
#define MTP   12      // padded row (floats)
#define NF    128
#define NKT   (NT*MT) // 160
#define REGc  0.1f

// ---------------- device scratch (no cudaMalloc allowed) ----------------
__device__ int      g_nbrs[NN * MM];
__device__ unsigned g_B[NN * MM];
__device__ unsigned g_mask[NN * MM];
__device__ float    g_f2n[NKT];
__device__ float    g_consts[3];     // cA = 2a/REG, cY = 4a/REG, cM = (1-a)/REG
__device__ float    g_D[NN * NKT];   // cM*(f2n[kt] - 2 * x[u] . F2[kt])

// packed f32x2 dot over 10 elements (both operands 16B-aligned smem rows)
__device__ __forceinline__ float dot10p(const float* __restrict__ a,
                                        const float* __restrict__ b) {
    const ulonglong2* A = (const ulonglong2*)a;
    const ulonglong2* B = (const ulonglong2*)b;
    ulonglong2 A0 = A[0], A1 = A[1];
    ulonglong2 B0 = B[0], B1 = B[1];
    unsigned long long a2 = *(const unsigned long long*)(a + 8);
    unsigned long long b2 = *(const unsigned long long*)(b + 8);
    unsigned long long acc;
    asm("mul.rn.f32x2 %0, %1, %2;"     : "=l"(acc) : "l"(A0.x), "l"(B0.x));
    asm("fma.rn.f32x2 %0, %1, %2, %0;" : "+l"(acc) : "l"(A0.y), "l"(B0.y));
    asm("fma.rn.f32x2 %0, %1, %2, %0;" : "+l"(acc) : "l"(A1.x), "l"(B1.x));
    asm("fma.rn.f32x2 %0, %1, %2, %0;" : "+l"(acc) : "l"(A1.y), "l"(B1.y));
    asm("fma.rn.f32x2 %0, %1, %2, %0;" : "+l"(acc) : "l"(a2),   "l"(b2));
    unsigned lo, hi;
    asm("mov.b64 {%0,%1}, %2;" : "=r"(lo), "=r"(hi) : "l"(acc));
    return __uint_as_float(lo) + __uint_as_float(hi);
}

// ---------------- setup: constants + |F2|^2 ----------------
__global__ void k_setup(const float* __restrict__ alpha0,
                        const float* __restrict__ F2) {
    int tid = threadIdx.x;
    if (tid == 0) {
        float a0 = alpha0[0];
        float alpha = 1.0f / (1.0f + __expf(-a0));
        g_consts[0] = 2.0f * alpha / REGc;
        g_consts[1] = 4.0f * alpha / REGc;
        g_consts[2] = (1.0f - alpha) / REGc;
    }
    for (int idx = tid; idx < NKT; idx += blockDim.x) {
        const float* row = F2 + (size_t)idx * NF;
        float s = 0.f;
        #pragma unroll 8
        for (int f = 0; f < NF; f++) { float v = row[f]; s += v * v; }
        g_f2n[idx] = s;
    }
}

// ---------------- GEMM: D = cM*(f2n - 2 * x @ F2^T) ----------------
__global__ void __launch_bounds__(256, 4)
k_gemm(const float* __restrict__ x, const float* __restrict__ F2) {
    __shared__ float sX[32][65];
    __shared__ float sF[32][161];

    const int tid = threadIdx.x;
    const int tr  = tid & 15;
    const int tc  = tid >> 4;
    const int r0  = blockIdx.x * 64;

    float acc[4][10];
    #pragma unroll
    for (int i = 0; i < 4; i++)
        #pragma unroll
        for (int j = 0; j < 10; j++) acc[i][j] = 0.f;

    for (int k0 = 0; k0 < NF; k0 += 32) {
        __syncthreads();
        for (int idx = tid; idx < 512; idx += 256) {
            int rr = idx >> 3, c4 = idx & 7;
            int gr = r0 + rr;
            float4 v = (gr < NN) ? __ldg((const float4*)(x + (size_t)gr * NF + k0) + c4)
                                 : make_float4(0.f, 0.f, 0.f, 0.f);
            sX[c4*4+0][rr] = v.x; sX[c4*4+1][rr] = v.y;
            sX[c4*4+2][rr] = v.z; sX[c4*4+3][rr] = v.w;
        }
        for (int idx = tid; idx < 1280; idx += 256) {
            int cc = idx >> 3, c4 = idx & 7;
            float4 v = __ldg((const float4*)(F2 + (size_t)cc * NF + k0) + c4);
            sF[c4*4+0][cc] = v.x; sF[c4*4+1][cc] = v.y;
            sF[c4*4+2][cc] = v.z; sF[c4*4+3][cc] = v.w;
        }
        __syncthreads();

        #pragma unroll 4
        for (int kk = 0; kk < 32; kk++) {
            float b[10];
            #pragma unroll
            for (int j = 0; j < 10; j++) b[j] = sF[kk][tc*10 + j];
            #pragma unroll
            for (int i = 0; i < 4; i++) {
                float a = sX[kk][tr + 16*i];
                #pragma unroll
                for (int j = 0; j < 10; j++) acc[i][j] = fmaf(a, b[j], acc[i][j]);
            }
        }
    }

    const float cM = g_consts[2];
    float f2c[10];
    #pragma unroll
    for (int j = 0; j < 10; j++) f2c[j] = g_f2n[tc*10 + j];
    #pragma unroll
    for (int i = 0; i < 4; i++) {
        int r = r0 + tr + 16*i;
        if (r < NN) {
            float* drow = g_D + (size_t)r * NKT + tc*10;
            #pragma unroll
            for (int j = 0; j < 10; j++)
                drow[j] = cM * (f2c[j] - 2.0f * acc[i][j]);
        }
    }
}

// ---------------- build directed-adjacency bitmasks B ----------------
__global__ void k_buildB(const int* __restrict__ dst) {
    int gid = blockIdx.x * blockDim.x + threadIdx.x;
    if (gid >= NN * MM) return;
    int n = gid / MM;
    int i = gid - n * MM;
    const int* dstn = dst + (size_t)n * DEG;
    int u = (i == 0) ? n : dstn[i - 1];
    g_nbrs[gid] = u;

    const int* dstu = dst + (size_t)u * DEG;
    int du[DEG];
    #pragma unroll
    for (int e = 0; e < DEG; e++) du[e] = dstu[e];
    int dn[DEG];
    #pragma unroll
    for (int e = 0; e < DEG; e++) dn[e] = dstn[e];

    unsigned bits = 0;
    #pragma unroll
    for (int j = 0; j < MM; j++) {
        int v = (j == 0) ? n : dn[j - 1];
        bool hit = false;
        #pragma unroll
        for (int e = 0; e < DEG; e++) hit |= (du[e] == v);
        bits |= (unsigned)hit << j;
    }
    g_B[gid] = bits;
}

// ---------------- symmetrize: C1 = B | B^T ----------------
__global__ void k_sym() {
    int gid = blockIdx.x * blockDim.x + threadIdx.x;
    if (gid >= NN * MM) return;
    int n = gid / MM;
    int i = gid - n * MM;
    unsigned mk = g_B[gid];
    const unsigned* Bn = g_B + n * MM;
    #pragma unroll
    for (int j = 0; j < MM; j++)
        mk |= ((Bn[j] >> i) & 1u) << j;
    g_mask[gid] = mk;
}

// ---------------- main: 10 mirror-descent iters + q ----------------
__global__ void __launch_bounds__(272, 3)
k_main(const float* __restrict__ C2g, float* __restrict__ out) {
    __shared__ __align__(16) float sT [NT][MM][MTP];
    __shared__ __align__(16) float sW [NT][MM][MTP];   // cY * C2 . T_b for listed pairs
    __shared__ __align__(16) float sC2 [NT][MT][MTP];
    __shared__ __align__(16) float sC2s[NT][MT][MTP];
    __shared__ __align__(16) float sq [NT][MTP];
    __shared__ __align__(16) float sU [NT][MTP];       // cY*W0 - cA*constC2   (m>=1)
    __shared__ __align__(16) float sU0[NT][MTP];       // cY*(Zq + c00w*W0) - cA*constC2 (m==0)
    __shared__ float sc00[NT];
    __shared__ int   sColMask[NT];
    __shared__ int   sList[NT * MM];
    __shared__ int   sLn;

    const int tid = threadIdx.x;
    const int n   = blockIdx.x;
    const int k   = tid / MM;
    const int m   = tid - k * MM;

    // cooperative load of C2 / C2^2 into padded smem
    for (int idx = tid; idx < NT * MT * MTP; idx += 272) {
        int kk = idx / (MT * MTP);
        int r  = idx - kk * MT * MTP;
        int s  = r / MTP;
        int t  = r - s * MTP;
        float v = (t < MT) ? C2g[(kk * MT + s) * MT + t] : 0.f;
        ((float*)sC2)[idx]  = v;
        ((float*)sC2s)[idx] = v * v;
    }
    if (tid < NT) sColMask[tid] = 0;

    const float cA = g_consts[0];
    const float cY = g_consts[1];

    // per-thread t-varying cost term (t-constant parts cancel in softmax)
    const int u = g_nbrs[n * MM + m];
    float basec[MT];
    {
        const float2* drow = (const float2*)(g_D + (size_t)u * NKT + k * MT);
        #pragma unroll
        for (int h = 0; h < 5; h++) {
            float2 v = __ldg(drow + h);
            basec[2*h]   = v.x;
            basec[2*h+1] = v.y;
        }
    }

    const unsigned mask = g_mask[n * MM + m];
    const unsigned resmask = (m == 0) ? 0u : (mask & ~1u);
    if (m == 0) sc00[k] = (mask & 1u) ? 0.f : -1.f;   // C1[0,0] - 1

    __syncthreads();
    if (resmask) atomicOr(&sColMask[k], (int)resmask);
    __syncthreads();
    if (tid == 0) {
        int L = 0;
        for (int kk = 0; kk < NT; kk++) {
            unsigned cm = (unsigned)sColMask[kk];
            while (cm) { int b = __ffs(cm) - 1; cm &= cm - 1; sList[L++] = (kk << 5) | b; }
        }
        sLn = L;
    }
    __syncthreads();
    const int L10 = 10 * sLn;

    float lt[MT];
    #pragma unroll
    for (int t = 0; t < MT; t++) lt[t] = 0.f;
    float e[MT];
    float w0own = 0.f;

    #pragma unroll 1
    for (int it = 0; it < 10; it++) {
        // softmax row in registers; T = p * softmax
        float mx = lt[0];
        #pragma unroll
        for (int t = 1; t < MT; t++) mx = fmaxf(mx, lt[t]);
        float ssum = 0.f;
        #pragma unroll
        for (int t = 0; t < MT; t++) { e[t] = __expf(lt[t] - mx); ssum += e[t]; }
        float pr = (1.0f / MM) / ssum;
        #pragma unroll
        for (int t = 0; t < MT; t++) e[t] *= pr;

        float* Trow = &sT[k][m][0];
        ((float4*)Trow)[0] = make_float4(e[0], e[1], e[2], e[3]);
        ((float4*)Trow)[1] = make_float4(e[4], e[5], e[6], e[7]);
        ((float2*)Trow)[4] = make_float2(e[8], e[9]);
        __syncthreads();   // A

        // lanes m<10: q column sum + shared W0[s] = C2[s] . T0
        if (m < MT) {
            float qv = 0.f;
            #pragma unroll
            for (int b = 0; b < MM; b++) qv += sT[k][b][m];
            sq[k][m] = qv;
            w0own = dot10p(&sC2[k][m][0], &sT[k][0][0]);
        }
        // worklist: residual W_b = cY * C2 . T_b, 10-lane parallel per pair
        for (int idx = tid; idx < L10; idx += 272) {
            int p = idx / 10;
            int s = idx - p * 10;
            int ent = sList[p];
            int kk = ent >> 5, b = ent & 31;
            sW[kk][b][s] = cY * dot10p(&sC2[kk][s][0], &sT[kk][b][0]);
        }
        __syncthreads();   // B

        // lanes m<10: Zq = C2 . q ; constC2 = C2s . q ; publish combined vectors
        if (m < MT) {
            float zq  = dot10p(&sC2 [k][m][0], &sq[k][0]);
            float cc  = dot10p(&sC2s[k][m][0], &sq[k][0]);
            float gcs = cA * cc;
            sU [k][m] = cY * w0own - gcs;
            sU0[k][m] = cY * fmaf(sc00[k], w0own, zq) - gcs;
        }
        __syncthreads();   // C

        // update: lt[s] += U[s] - basec[s] (+ rare residual rows)
        const float* Ur = (m == 0) ? &sU0[k][0] : &sU[k][0];
        float4 u0 = *(const float4*)Ur;
        float4 u1 = *(const float4*)(Ur + 4);
        float2 u2 = *(const float2*)(Ur + 8);
        lt[0] += u0.x - basec[0]; lt[1] += u0.y - basec[1];
        lt[2] += u0.z - basec[2]; lt[3] += u0.w - basec[3];
        lt[4] += u1.x - basec[4]; lt[5] += u1.y - basec[5];
        lt[6] += u1.z - basec[6]; lt[7] += u1.w - basec[7];
        lt[8] += u2.x - basec[8]; lt[9] += u2.y - basec[9];

        unsigned rm = resmask;
        while (rm) {
            int b = __ffs(rm) - 1; rm &= rm - 1;
            const float* Wr = &sW[k][b][0];
            float4 w0v = *(const float4*)Wr;
            float4 w1v = *(const float4*)(Wr + 4);
            float2 w2v = *(const float2*)(Wr + 8);
            lt[0] += w0v.x; lt[1] += w0v.y; lt[2] += w0v.z; lt[3] += w0v.w;
            lt[4] += w1v.x; lt[5] += w1v.y; lt[6] += w1v.z; lt[7] += w1v.w;
            lt[8] += w2v.x; lt[9] += w2v.y;
        }
    }

    // final marginal q from one more softmax
    {
        float mx = lt[0];
        #pragma unroll
        for (int t = 1; t < MT; t++) mx = fmaxf(mx, lt[t]);
        float ssum = 0.f;
        #pragma unroll
        for (int t = 0; t < MT; t++) { e[t] = __expf(lt[t] - mx); ssum += e[t]; }
        float pr = (1.0f / MM) / ssum;
        #pragma unroll
        for (int t = 0; t < MT; t++) e[t] *= pr;
        float* Trow = &sT[k][m][0];
        ((float4*)Trow)[0] = make_float4(e[0], e[1], e[2], e[3]);
        ((float4*)Trow)[1] = make_float4(e[4], e[5], e[6], e[7]);
        ((float2*)Trow)[4] = make_float2(e[8], e[9]);
        __syncthreads();
        if (m < MT) {
            float qv = 0.f;
            #pragma unroll
            for (int b = 0; b < MM; b++) qv += sT[k][b][m];
            out[(size_t)n * NKT + k * MT + m] = qv;
        }
    }
}

// ---------------- launch ----------------
extern "C" void kernel_launch(void* const* d_in, const int* in_sizes, int n_in,
                              void* d_out, int out_size) {
    const float* x      = (const float*)d_in[0];
    const int*   eidx   = (const int*)d_in[1];
    const float* C2g    = (const float*)d_in[2];
    const float* F2     = (const float*)d_in[3];
    const float* alpha0 = (const float*)d_in[4];
    float* out = (float*)d_out;

    const int* dst = eidx + NN * DEG;   // row 1 of edge_index

    k_setup<<<1, 256>>>(alpha0, F2);
    k_gemm<<<(NN + 63) / 64, 256>>>(x, F2);
    int tot = NN * MM;
    k_buildB<<<(tot + 127) / 128, 128>>>(dst);
    k_sym<<<(tot + 127) / 128, 128>>>();
    k_main<<<NN, 272>>>(C2g, out);
}